// round 4
// baseline (speedup 1.0000x reference)
#include <cuda_runtime.h>

// Problem dims (fixed by the reference)
constexpr int B_  = 32;
constexpr int D_  = 256;   // idf
constexpr int Q_  = 1024;  // ih*iw
constexpr int C_  = 512;   // cdf
constexpr int L_  = 128;
constexpr int N_  = 10;    // contexts
constexpr int K2_ = N_ * L_;  // 1280

// Scratch (static device globals — no allocation in kernel_launch)
__device__ float g_tgt[(size_t)B_ * Q_ * D_];          //  [b][q][d]
__device__ float g_src[(size_t)N_ * B_ * L_ * D_];     //  [n][b][l][d]
__device__ float g_w  [(size_t)B_ * Q_ * N_ * L_];     //  [b][q][n][l]
__device__ float g_s2 [(size_t)B_ * D_ * N_ * L_];     //  [b][e][n][l]

typedef unsigned long long u64;

// ---- packed f32x2 helpers (FFMA2: ptxas never emits this from C++) ----
__device__ __forceinline__ u64 packbc(float x) {
    u64 r; asm("mov.b64 %0, {%1, %1};" : "=l"(r) : "f"(x)); return r;
}
__device__ __forceinline__ void ffma2(u64& d, u64 a, u64 b) {
    asm("fma.rn.f32x2 %0, %1, %2, %0;" : "+l"(d) : "l"(a), "l"(b));
}
__device__ __forceinline__ float2 unpk(u64 v) {
    float lo, hi; asm("mov.b64 {%0, %1}, %2;" : "=f"(lo), "=f"(hi) : "l"(v));
    return make_float2(lo, hi);
}

// 8 rows x 8 cols (4 packed pairs) outer-product accumulate
__device__ __forceinline__ void fma8x8p(u64 (&acc)[8][4], float4 a0, float4 a1,
                                        const u64 (&bv)[4]) {
    float av[8] = {a0.x, a0.y, a0.z, a0.w, a1.x, a1.y, a1.z, a1.w};
    #pragma unroll
    for (int i = 0; i < 8; i++) {
        u64 ap = packbc(av[i]);
        #pragma unroll
        for (int j = 0; j < 4; j++) ffma2(acc[i][j], ap, bv[j]);
    }
}

__device__ __forceinline__ float warpSum16(float v) {
    #pragma unroll
    for (int o = 8; o; o >>= 1) v += __shfl_xor_sync(0xffffffffu, v, o);
    return v;
}
__device__ __forceinline__ float warpMax16(float v) {
    #pragma unroll
    for (int o = 8; o; o >>= 1) v = fmaxf(v, __shfl_xor_sync(0xffffffffu, v, o));
    return v;
}
__device__ __forceinline__ float warpSum32(float v) {
    #pragma unroll
    for (int o = 16; o; o >>= 1) v += __shfl_xor_sync(0xffffffffu, v, o);
    return v;
}

// ---------------------------------------------------------------------------
// K1: transpose input [B][D][Q] -> g_tgt [B][Q][D]
// ---------------------------------------------------------------------------
__global__ void __launch_bounds__(256) k_transpose(const float* __restrict__ in) {
    __shared__ float tile[32][33];
    const int b  = blockIdx.z;
    const int q0 = blockIdx.x * 32;
    const int d0 = blockIdx.y * 32;
    const int tx = threadIdx.x, ty = threadIdx.y;  // 32 x 8
    #pragma unroll
    for (int j = 0; j < 4; j++)
        tile[ty + j * 8][tx] = in[((size_t)b * D_ + d0 + ty + j * 8) * Q_ + q0 + tx];
    __syncthreads();
    #pragma unroll
    for (int j = 0; j < 4; j++)
        g_tgt[((size_t)b * Q_ + q0 + ty + j * 8) * D_ + d0 + tx] = tile[tx][ty + j * 8];
}

// ---------------------------------------------------------------------------
// K2: per (n,b): src[l,d] = sum_c ctx[c,l] * Wc[d,c]
// CTA tile: 128 l x 128 d, kc = 32, pipelined double buffer. grid (2, N*B)
// ---------------------------------------------------------------------------
__global__ void __launch_bounds__(256) k_source(const float* __restrict__ ctx,
                                                const float* __restrict__ Wc) {
    const int nb = blockIdx.y;
    const int d0 = blockIdx.x * 128;
    const float* ctxp = ctx + (size_t)nb * C_ * L_;  // [C][L]
    __shared__ __align__(16) float a_s[2][32][132];   // [c][l]
    __shared__ __align__(16) float b_s[2][32][132];   // [c][d]
    const int t  = threadIdx.x;
    const int ty = t >> 4, tx = t & 15;
    u64 acc[8][4] = {};
    constexpr int NC = C_ / 32;   // 16

    float4 ar[4], br[4];
    auto load_regs = [&](int kc) {
        #pragma unroll
        for (int i = 0; i < 4; i++) {
            int idx = t + i * 256;               // A: 32c x 32(l4)
            int c = idx >> 5, l4 = idx & 31;
            ar[i] = *(const float4*)&ctxp[(size_t)(kc + c) * L_ + l4 * 4];
        }
        #pragma unroll
        for (int i = 0; i < 4; i++) {
            int idx = t + i * 256;               // B: 128d x 8(c4)
            int d = idx >> 3, c4 = (idx & 7) * 4;
            br[i] = *(const float4*)&Wc[(size_t)(d0 + d) * C_ + kc + c4];
        }
    };
    auto store_smem = [&](int buf) {
        #pragma unroll
        for (int i = 0; i < 4; i++) {
            int idx = t + i * 256;
            int c = idx >> 5, l4 = idx & 31;
            *(float4*)&a_s[buf][c][l4 * 4] = ar[i];
        }
        #pragma unroll
        for (int i = 0; i < 4; i++) {
            int idx = t + i * 256;
            int d = idx >> 3, c4 = (idx & 7) * 4;
            b_s[buf][c4 + 0][d] = br[i].x; b_s[buf][c4 + 1][d] = br[i].y;
            b_s[buf][c4 + 2][d] = br[i].z; b_s[buf][c4 + 3][d] = br[i].w;
        }
    };

    load_regs(0);
    store_smem(0);
    __syncthreads();
    for (int ch = 0; ch < NC; ch++) {
        if (ch + 1 < NC) load_regs((ch + 1) * 32);
        const int buf = ch & 1;
        #pragma unroll
        for (int c = 0; c < 32; c++) {
            float4 a0 = *(const float4*)&a_s[buf][c][ty * 4];
            float4 a1 = *(const float4*)&a_s[buf][c][ty * 4 + 64];
            const u64* p0 = (const u64*)&b_s[buf][c][tx * 4];
            const u64* p1 = (const u64*)&b_s[buf][c][tx * 4 + 64];
            u64 bv[4] = {p0[0], p0[1], p1[0], p1[1]};
            fma8x8p(acc, a0, a1, bv);
        }
        if (ch + 1 < NC) {
            store_smem(buf ^ 1);
            __syncthreads();
        }
    }
    float* outp = g_src + (size_t)nb * L_ * D_;
    #pragma unroll
    for (int h = 0; h < 2; h++)
        #pragma unroll
        for (int i = 0; i < 4; i++) {
            int l = h * 64 + ty * 4 + i;
            u64* a = acc[h * 4 + i];
            float2 r0 = unpk(a[0]), r1 = unpk(a[1]), r2 = unpk(a[2]), r3 = unpk(a[3]);
            *(float4*)&outp[(size_t)l * D_ + d0 + tx * 4] = make_float4(r0.x, r0.y, r1.x, r1.y);
            *(float4*)&outp[(size_t)l * D_ + d0 + 64 + tx * 4] = make_float4(r2.x, r2.y, r3.x, r3.y);
        }
}

// ---------------------------------------------------------------------------
// K3: per (n,b): logits[q,l] = sum_d tgt[q,d]*src[l,d]; softmax over L;
//     CTA tile 128 q x 128 l, kc = 32, pipelined. grid (8, N*B)
// ---------------------------------------------------------------------------
__global__ void __launch_bounds__(256) k_attn() {
    const int nb = blockIdx.y;
    const int n = nb >> 5, b = nb & 31;
    const int q0 = blockIdx.x * 128;
    const float* tgt = g_tgt + (size_t)b * Q_ * D_;
    const float* src = g_src + (size_t)nb * L_ * D_;
    __shared__ __align__(16) float a_s[2][32][132];   // [d][q]
    __shared__ __align__(16) float b_s[2][32][132];   // [d][l]
    const int t  = threadIdx.x;
    const int ty = t >> 4, tx = t & 15;
    u64 acc[8][4] = {};
    constexpr int NC = D_ / 32;   // 8

    float4 ar[4], br[4];
    auto load_regs = [&](int kd) {
        #pragma unroll
        for (int i = 0; i < 4; i++) {
            int idx = t + i * 256;               // A: 128q x 8(d4)
            int q = idx >> 3, d4 = (idx & 7) * 4;
            ar[i] = *(const float4*)&tgt[(size_t)(q0 + q) * D_ + kd + d4];
        }
        #pragma unroll
        for (int i = 0; i < 4; i++) {
            int idx = t + i * 256;               // B: 128l x 8(d4)
            int l = idx >> 3, d4 = (idx & 7) * 4;
            br[i] = *(const float4*)&src[(size_t)l * D_ + kd + d4];
        }
    };
    auto store_smem = [&](int buf) {
        #pragma unroll
        for (int i = 0; i < 4; i++) {
            int idx = t + i * 256;
            int q = idx >> 3, d4 = (idx & 7) * 4;
            a_s[buf][d4 + 0][q] = ar[i].x; a_s[buf][d4 + 1][q] = ar[i].y;
            a_s[buf][d4 + 2][q] = ar[i].z; a_s[buf][d4 + 3][q] = ar[i].w;
        }
        #pragma unroll
        for (int i = 0; i < 4; i++) {
            int idx = t + i * 256;
            int l = idx >> 3, d4 = (idx & 7) * 4;
            b_s[buf][d4 + 0][l] = br[i].x; b_s[buf][d4 + 1][l] = br[i].y;
            b_s[buf][d4 + 2][l] = br[i].z; b_s[buf][d4 + 3][l] = br[i].w;
        }
    };

    load_regs(0);
    store_smem(0);
    __syncthreads();
    for (int ch = 0; ch < NC; ch++) {
        if (ch + 1 < NC) load_regs((ch + 1) * 32);
        const int buf = ch & 1;
        #pragma unroll
        for (int d = 0; d < 32; d++) {
            float4 a0 = *(const float4*)&a_s[buf][d][ty * 4];
            float4 a1 = *(const float4*)&a_s[buf][d][ty * 4 + 64];
            const u64* p0 = (const u64*)&b_s[buf][d][tx * 4];
            const u64* p1 = (const u64*)&b_s[buf][d][tx * 4 + 64];
            u64 bv[4] = {p0[0], p0[1], p1[0], p1[1]};
            fma8x8p(acc, a0, a1, bv);
        }
        if (ch + 1 < NC) {
            store_smem(buf ^ 1);
            __syncthreads();
        }
    }
    // softmax over l per q-row (16 lanes share a row; 8 l per lane)
    #pragma unroll
    for (int h = 0; h < 2; h++)
        #pragma unroll
        for (int i = 0; i < 4; i++) {
            u64* a = acc[h * 4 + i];
            float2 r0 = unpk(a[0]), r1 = unpk(a[1]), r2 = unpk(a[2]), r3 = unpk(a[3]);
            float v[8] = {r0.x, r0.y, r1.x, r1.y, r2.x, r2.y, r3.x, r3.y};
            float m = v[0];
            #pragma unroll
            for (int j = 1; j < 8; j++) m = fmaxf(m, v[j]);
            m = warpMax16(m);
            float e[8], s = 0.f;
            #pragma unroll
            for (int j = 0; j < 8; j++) { e[j] = __expf(v[j] - m); s += e[j]; }
            s = warpSum16(s);
            float inv = 1.0f / s;
            int q = q0 + h * 64 + ty * 4 + i;
            float* wrow = g_w + (((size_t)b * Q_ + q) * N_ + n) * L_;
            *(float4*)&wrow[tx * 4] =
                make_float4(e[0] * inv, e[1] * inv, e[2] * inv, e[3] * inv);
            *(float4*)&wrow[64 + tx * 4] =
                make_float4(e[4] * inv, e[5] * inv, e[6] * inv, e[7] * inv);
        }
}

// ---------------------------------------------------------------------------
// K4: per (n,b): S2[e,l] = sum_d Wcat[e, n*D+d] * src[l,d] -> g_s2[b][e][n][l]
// CTA tile 128 e x 128 l, kc = 32, pipelined.  grid (2, N*B)
// ---------------------------------------------------------------------------
__global__ void __launch_bounds__(256) k_s2(const float* __restrict__ Wcat) {
    const int nb = blockIdx.y;
    const int n = nb >> 5, b = nb & 31;
    const int e0 = blockIdx.x * 128;
    const float* src = g_src + (size_t)nb * L_ * D_;
    __shared__ __align__(16) float a_s[2][32][132];   // [d][e]
    __shared__ __align__(16) float b_s[2][32][132];   // [d][l]
    const int t  = threadIdx.x;
    const int ty = t >> 4, tx = t & 15;
    u64 acc[8][4] = {};
    constexpr int NC = D_ / 32;   // 8

    float4 ar[4], br[4];
    auto load_regs = [&](int kd) {
        #pragma unroll
        for (int i = 0; i < 4; i++) {
            int idx = t + i * 256;               // A: 128e x 8(d4)
            int e = idx >> 3, d4 = (idx & 7) * 4;
            ar[i] = *(const float4*)&Wcat[(size_t)(e0 + e) * (N_ * D_) + n * D_ + kd + d4];
        }
        #pragma unroll
        for (int i = 0; i < 4; i++) {
            int idx = t + i * 256;               // B: 128l x 8(d4)
            int l = idx >> 3, d4 = (idx & 7) * 4;
            br[i] = *(const float4*)&src[(size_t)l * D_ + kd + d4];
        }
    };
    auto store_smem = [&](int buf) {
        #pragma unroll
        for (int i = 0; i < 4; i++) {
            int idx = t + i * 256;
            int e = idx >> 3, d4 = (idx & 7) * 4;
            a_s[buf][d4 + 0][e] = ar[i].x; a_s[buf][d4 + 1][e] = ar[i].y;
            a_s[buf][d4 + 2][e] = ar[i].z; a_s[buf][d4 + 3][e] = ar[i].w;
        }
        #pragma unroll
        for (int i = 0; i < 4; i++) {
            int idx = t + i * 256;
            int l = idx >> 3, d4 = (idx & 7) * 4;
            b_s[buf][d4 + 0][l] = br[i].x; b_s[buf][d4 + 1][l] = br[i].y;
            b_s[buf][d4 + 2][l] = br[i].z; b_s[buf][d4 + 3][l] = br[i].w;
        }
    };

    load_regs(0);
    store_smem(0);
    __syncthreads();
    for (int ch = 0; ch < NC; ch++) {
        if (ch + 1 < NC) load_regs((ch + 1) * 32);
        const int buf = ch & 1;
        #pragma unroll
        for (int d = 0; d < 32; d++) {
            float4 a0 = *(const float4*)&a_s[buf][d][ty * 4];
            float4 a1 = *(const float4*)&a_s[buf][d][ty * 4 + 64];
            const u64* p0 = (const u64*)&b_s[buf][d][tx * 4];
            const u64* p1 = (const u64*)&b_s[buf][d][tx * 4 + 64];
            u64 bv[4] = {p0[0], p0[1], p1[0], p1[1]};
            fma8x8p(acc, a0, a1, bv);
        }
        if (ch + 1 < NC) {
            store_smem(buf ^ 1);
            __syncthreads();
        }
    }
    #pragma unroll
    for (int h = 0; h < 2; h++)
        #pragma unroll
        for (int i = 0; i < 4; i++) {
            int e = e0 + h * 64 + ty * 4 + i;
            float* srow = g_s2 + (((size_t)b * D_ + e) * N_ + n) * L_;
            u64* a = acc[h * 4 + i];
            float2 r0 = unpk(a[0]), r1 = unpk(a[1]), r2 = unpk(a[2]), r3 = unpk(a[3]);
            *(float4*)&srow[tx * 4]      = make_float4(r0.x, r0.y, r1.x, r1.y);
            *(float4*)&srow[64 + tx * 4] = make_float4(r2.x, r2.y, r3.x, r3.y);
        }
}

// ---------------------------------------------------------------------------
// K5: per b: x[q,e] = sum_k w[b,q,k] * s2[b,e,k]  (K = 1280), pipelined.
//     epilogue: + Wb, relu, + tgt, LayerNorm(eps=0) * gamma + beta -> out
// CTA tile 64 q x 256 e, kc = 16.  Each warp: 8 q rows, full 256-e row.
// ---------------------------------------------------------------------------
__global__ void __launch_bounds__(256) k_out(const float* __restrict__ Wb,
                                             const float* __restrict__ gamma,
                                             const float* __restrict__ beta,
                                             float* __restrict__ out) {
    const int b  = blockIdx.y;
    const int q0 = blockIdx.x * 64;
    const float* wp = g_w  + (size_t)b * Q_ * K2_;
    const float* sp = g_s2 + (size_t)b * D_ * K2_;
    __shared__ __align__(16) float a_s[2][16][68];    // [k][q]  (64 q)
    __shared__ __align__(16) float b_s[2][16][260];   // [k][e]  (256 e)
    const int t  = threadIdx.x;
    const int ty = t >> 5, tx = t & 31;
    u64 acc[8][4] = {};
    constexpr int NC = K2_ / 16;   // 80

    float4 ar, br[4];
    auto load_regs = [&](int k0) {
        {
            int q = t >> 2, k4 = (t & 3) * 4;    // A: 64q x 4(k4)
            ar = *(const float4*)&wp[(size_t)(q0 + q) * K2_ + k0 + k4];
        }
        #pragma unroll
        for (int i = 0; i < 4; i++) {
            int idx = t + i * 256;               // B: 256e x 4(k4)
            int e = idx >> 2, k4 = (idx & 3) * 4;
            br[i] = *(const float4*)&sp[(size_t)e * K2_ + k0 + k4];
        }
    };
    auto store_smem = [&](int buf) {
        {
            int q = t >> 2, k4 = (t & 3) * 4;
            a_s[buf][k4 + 0][q] = ar.x; a_s[buf][k4 + 1][q] = ar.y;
            a_s[buf][k4 + 2][q] = ar.z; a_s[buf][k4 + 3][q] = ar.w;
        }
        #pragma unroll
        for (int i = 0; i < 4; i++) {
            int idx = t + i * 256;
            int e = idx >> 2, k4 = (idx & 3) * 4;
            b_s[buf][k4 + 0][e] = br[i].x; b_s[buf][k4 + 1][e] = br[i].y;
            b_s[buf][k4 + 2][e] = br[i].z; b_s[buf][k4 + 3][e] = br[i].w;
        }
    };

    load_regs(0);
    store_smem(0);
    __syncthreads();
    for (int ch = 0; ch < NC; ch++) {
        if (ch + 1 < NC) load_regs((ch + 1) * 16);
        const int buf = ch & 1;
        #pragma unroll
        for (int k = 0; k < 16; k++) {
            float4 a0 = *(const float4*)&a_s[buf][k][ty * 8];
            float4 a1 = *(const float4*)&a_s[buf][k][ty * 8 + 4];
            const u64* p0 = (const u64*)&b_s[buf][k][tx * 4];
            const u64* p1 = (const u64*)&b_s[buf][k][tx * 4 + 128];
            u64 bv[4] = {p0[0], p0[1], p1[0], p1[1]};
            fma8x8p(acc, a0, a1, bv);
        }
        if (ch + 1 < NC) {
            store_smem(buf ^ 1);
            __syncthreads();
        }
    }
    // epilogue
    float wb[8], gm[8], be[8];
    {
        float4 w0 = *(const float4*)&Wb[tx * 4];
        float4 w1 = *(const float4*)&Wb[tx * 4 + 128];
        float4 g0 = *(const float4*)&gamma[tx * 4];
        float4 g1 = *(const float4*)&gamma[tx * 4 + 128];
        float4 e0 = *(const float4*)&beta[tx * 4];
        float4 e1 = *(const float4*)&beta[tx * 4 + 128];
        wb[0]=w0.x; wb[1]=w0.y; wb[2]=w0.z; wb[3]=w0.w; wb[4]=w1.x; wb[5]=w1.y; wb[6]=w1.z; wb[7]=w1.w;
        gm[0]=g0.x; gm[1]=g0.y; gm[2]=g0.z; gm[3]=g0.w; gm[4]=g1.x; gm[5]=g1.y; gm[6]=g1.z; gm[7]=g1.w;
        be[0]=e0.x; be[1]=e0.y; be[2]=e0.z; be[3]=e0.w; be[4]=e1.x; be[5]=e1.y; be[6]=e1.z; be[7]=e1.w;
    }
    const float* tgt = g_tgt + (size_t)b * Q_ * D_;
    #pragma unroll
    for (int i = 0; i < 8; i++) {
        const int q = q0 + ty * 8 + i;
        u64* a = acc[i];
        float2 r0 = unpk(a[0]), r1 = unpk(a[1]), r2 = unpk(a[2]), r3 = unpk(a[3]);
        float av[8] = {r0.x, r0.y, r1.x, r1.y, r2.x, r2.y, r3.x, r3.y};
        float4 t0 = *(const float4*)&tgt[(size_t)q * D_ + tx * 4];
        float4 t1 = *(const float4*)&tgt[(size_t)q * D_ + tx * 4 + 128];
        float tv[8] = {t0.x, t0.y, t0.z, t0.w, t1.x, t1.y, t1.z, t1.w};
        float v[8], s = 0.f;
        #pragma unroll
        for (int j = 0; j < 8; j++) {
            v[j] = fmaxf(av[j] + wb[j], 0.f) + tv[j];
            s += v[j];
        }
        s = warpSum32(s);
        const float mu = s * (1.0f / 256.0f);
        float d2 = 0.f;
        #pragma unroll
        for (int j = 0; j < 8; j++) { float dd = v[j] - mu; d2 += dd * dd; }
        d2 = warpSum32(d2);
        const float rs = rsqrtf(d2 * (1.0f / 256.0f));
        float o[8];
        #pragma unroll
        for (int j = 0; j < 8; j++) o[j] = (v[j] - mu) * rs * gm[j] + be[j];
        float* orow = out + (size_t)(b * Q_ + q) * D_;
        *(float4*)&orow[tx * 4]       = make_float4(o[0], o[1], o[2], o[3]);
        *(float4*)&orow[tx * 4 + 128] = make_float4(o[4], o[5], o[6], o[7]);
    }
}

// ---------------------------------------------------------------------------
extern "C" void kernel_launch(void* const* d_in, const int* in_sizes, int n_in,
                              void* d_out, int out_size) {
    const float* input    = (const float*)d_in[0];  // [B, D, 32, 32]
    const float* contexts = (const float*)d_in[1];  // [N, B, C, L]
    const float* Wc       = (const float*)d_in[2];  // [D, C]
    const float* Wcat     = (const float*)d_in[3];  // [D, N*D]
    const float* Wb       = (const float*)d_in[4];  // [D]
    const float* gamma    = (const float*)d_in[5];  // [D]
    const float* beta     = (const float*)d_in[6];  // [D]
    float* out = (float*)d_out;                     // [B, Q, D]

    k_transpose<<<dim3(Q_ / 32, D_ / 32, B_), dim3(32, 8)>>>(input);
    k_source   <<<dim3(2,        N_ * B_),    256>>>(contexts, Wc);
    k_attn     <<<dim3(Q_ / 128, N_ * B_),    256>>>();
    k_s2       <<<dim3(2,        N_ * B_),    256>>>(Wcat);
    k_out      <<<dim3(Q_ / 64,  B_),         256>>>(Wb, gamma, beta, out);
}

// round 5
// speedup vs baseline: 1.1419x; 1.1419x over previous
#include <cuda_runtime.h>

// Problem dims (fixed by the reference)
constexpr int B_  = 32;
constexpr int D_  = 256;   // idf
constexpr int Q_  = 1024;  // ih*iw
constexpr int C_  = 512;   // cdf
constexpr int L_  = 128;
constexpr int N_  = 10;    // contexts
constexpr int K2_ = N_ * L_;  // 1280

// Scratch (static device globals — no allocation in kernel_launch)
__device__ float g_tgt[(size_t)B_ * Q_ * D_];          //  [b][q][d]
__device__ float g_src[(size_t)N_ * B_ * L_ * D_];     //  [n][b][l][d]
__device__ float g_w  [(size_t)B_ * Q_ * N_ * L_];     //  [b][q][n][l]
__device__ float g_s2 [(size_t)B_ * D_ * N_ * L_];     //  [b][e][n][l]

typedef unsigned long long u64;

// ---- packed f32x2 helpers (FFMA2: ptxas never emits this from C++) ----
__device__ __forceinline__ u64 packbc(float x) {
    u64 r; asm("mov.b64 %0, {%1, %1};" : "=l"(r) : "f"(x)); return r;
}
__device__ __forceinline__ void ffma2(u64& d, u64 a, u64 b) {
    asm("fma.rn.f32x2 %0, %1, %2, %0;" : "+l"(d) : "l"(a), "l"(b));
}
__device__ __forceinline__ float2 unpk(u64 v) {
    float lo, hi; asm("mov.b64 {%0, %1}, %2;" : "=f"(lo), "=f"(hi) : "l"(v));
    return make_float2(lo, hi);
}

// 8 rows x 8 cols (4 packed pairs) outer-product accumulate
__device__ __forceinline__ void fma8x8p(u64 (&acc)[8][4], float4 a0, float4 a1,
                                        const u64 (&bv)[4]) {
    float av[8] = {a0.x, a0.y, a0.z, a0.w, a1.x, a1.y, a1.z, a1.w};
    #pragma unroll
    for (int i = 0; i < 8; i++) {
        u64 ap = packbc(av[i]);
        #pragma unroll
        for (int j = 0; j < 4; j++) ffma2(acc[i][j], ap, bv[j]);
    }
}

__device__ __forceinline__ float warpSum16(float v) {
    #pragma unroll
    for (int o = 8; o; o >>= 1) v += __shfl_xor_sync(0xffffffffu, v, o);
    return v;
}
__device__ __forceinline__ float warpMax16(float v) {
    #pragma unroll
    for (int o = 8; o; o >>= 1) v = fmaxf(v, __shfl_xor_sync(0xffffffffu, v, o));
    return v;
}
__device__ __forceinline__ float warpSum32(float v) {
    #pragma unroll
    for (int o = 16; o; o >>= 1) v += __shfl_xor_sync(0xffffffffu, v, o);
    return v;
}

// ---------------------------------------------------------------------------
// K1: transpose input [B][D][Q] -> g_tgt [B][Q][D]
// ---------------------------------------------------------------------------
__global__ void __launch_bounds__(256) k_transpose(const float* __restrict__ in) {
    __shared__ float tile[32][33];
    const int b  = blockIdx.z;
    const int q0 = blockIdx.x * 32;
    const int d0 = blockIdx.y * 32;
    const int tx = threadIdx.x, ty = threadIdx.y;  // 32 x 8
    #pragma unroll
    for (int j = 0; j < 4; j++)
        tile[ty + j * 8][tx] = in[((size_t)b * D_ + d0 + ty + j * 8) * Q_ + q0 + tx];
    __syncthreads();
    #pragma unroll
    for (int j = 0; j < 4; j++)
        g_tgt[((size_t)b * Q_ + q0 + ty + j * 8) * D_ + d0 + tx] = tile[tx][ty + j * 8];
}

// ---------------------------------------------------------------------------
// K2: per (n,b): src[l,d] = sum_c ctx[c,l] * Wc[d,c]
// CTA tile: 128 l x 128 d (full L), kc = 32.  grid (2, N*B)
// ---------------------------------------------------------------------------
__global__ void __launch_bounds__(256, 2) k_source(const float* __restrict__ ctx,
                                                   const float* __restrict__ Wc) {
    const int nb = blockIdx.y;
    const int d0 = blockIdx.x * 128;
    const float* ctxp = ctx + (size_t)nb * C_ * L_;  // [C][L]
    __shared__ __align__(16) float a_s[32][132];   // [c][l]
    __shared__ __align__(16) float b_s[32][132];   // [c][d]
    const int t  = threadIdx.x;
    const int ty = t >> 4, tx = t & 15;
    u64 acc[8][4] = {};
    for (int kc = 0; kc < C_; kc += 32) {
        __syncthreads();
        // A: ctx[c][l] direct (rows l-contiguous)
        #pragma unroll
        for (int i = 0; i < 4; i++) {
            int idx = t + i * 256;               // 1024 float4 = 32c x 128l
            int c = idx >> 5, l4 = idx & 31;
            *(float4*)&a_s[c][l4 * 4] = *(const float4*)&ctxp[(size_t)(kc + c) * L_ + l4 * 4];
        }
        // B: Wc[d][c] transposed (load float4 along c)
        #pragma unroll
        for (int i = 0; i < 4; i++) {
            int idx = t + i * 256;               // 1024 float4 = 128d x 8(c4)
            int d = idx >> 3, c4 = (idx & 7) * 4;
            float4 v = *(const float4*)&Wc[(size_t)(d0 + d) * C_ + kc + c4];
            b_s[c4 + 0][d] = v.x; b_s[c4 + 1][d] = v.y;
            b_s[c4 + 2][d] = v.z; b_s[c4 + 3][d] = v.w;
        }
        __syncthreads();
        #pragma unroll
        for (int c = 0; c < 32; c++) {
            float4 a0 = *(const float4*)&a_s[c][ty * 4];
            float4 a1 = *(const float4*)&a_s[c][ty * 4 + 64];
            const u64* p0 = (const u64*)&b_s[c][tx * 4];
            const u64* p1 = (const u64*)&b_s[c][tx * 4 + 64];
            u64 bv[4] = {p0[0], p0[1], p1[0], p1[1]};
            fma8x8p(acc, a0, a1, bv);
        }
    }
    float* outp = g_src + (size_t)nb * L_ * D_;
    #pragma unroll
    for (int h = 0; h < 2; h++)
        #pragma unroll
        for (int i = 0; i < 4; i++) {
            int l = h * 64 + ty * 4 + i;
            u64* a = acc[h * 4 + i];
            float2 r0 = unpk(a[0]), r1 = unpk(a[1]), r2 = unpk(a[2]), r3 = unpk(a[3]);
            *(float4*)&outp[(size_t)l * D_ + d0 + tx * 4] = make_float4(r0.x, r0.y, r1.x, r1.y);
            *(float4*)&outp[(size_t)l * D_ + d0 + 64 + tx * 4] = make_float4(r2.x, r2.y, r3.x, r3.y);
        }
}

// ---------------------------------------------------------------------------
// K3: per (n,b): logits[q,l] = sum_d tgt[q,d]*src[l,d]; softmax over L;
//     write w to g_w[b][q][n][l].  CTA tile 128 q x 128 l, kc = 32. grid (8, N*B)
// ---------------------------------------------------------------------------
__global__ void __launch_bounds__(256, 2) k_attn() {
    const int nb = blockIdx.y;
    const int n = nb >> 5, b = nb & 31;
    const int q0 = blockIdx.x * 128;
    const float* tgt = g_tgt + (size_t)b * Q_ * D_;
    const float* src = g_src + (size_t)nb * L_ * D_;
    __shared__ __align__(16) float a_s[32][132];   // [d][q]
    __shared__ __align__(16) float b_s[32][132];   // [d][l]
    const int t  = threadIdx.x;
    const int ty = t >> 4, tx = t & 15;
    u64 acc[8][4] = {};
    for (int kd = 0; kd < D_; kd += 32) {
        __syncthreads();
        #pragma unroll
        for (int i = 0; i < 4; i++) {
            int idx = t + i * 256;               // 128q x 8(d4)
            int q = idx >> 3, d4 = (idx & 7) * 4;
            float4 v = *(const float4*)&tgt[(size_t)(q0 + q) * D_ + kd + d4];
            a_s[d4 + 0][q] = v.x; a_s[d4 + 1][q] = v.y;
            a_s[d4 + 2][q] = v.z; a_s[d4 + 3][q] = v.w;
        }
        #pragma unroll
        for (int i = 0; i < 4; i++) {
            int idx = t + i * 256;               // 128l x 8(d4)
            int l = idx >> 3, d4 = (idx & 7) * 4;
            float4 v = *(const float4*)&src[(size_t)l * D_ + kd + d4];
            b_s[d4 + 0][l] = v.x; b_s[d4 + 1][l] = v.y;
            b_s[d4 + 2][l] = v.z; b_s[d4 + 3][l] = v.w;
        }
        __syncthreads();
        #pragma unroll
        for (int d = 0; d < 32; d++) {
            float4 a0 = *(const float4*)&a_s[d][ty * 4];
            float4 a1 = *(const float4*)&a_s[d][ty * 4 + 64];
            const u64* p0 = (const u64*)&b_s[d][tx * 4];
            const u64* p1 = (const u64*)&b_s[d][tx * 4 + 64];
            u64 bv[4] = {p0[0], p0[1], p1[0], p1[1]};
            fma8x8p(acc, a0, a1, bv);
        }
    }
    // softmax over l per q-row (16 lanes share a row; 8 l per lane)
    #pragma unroll
    for (int h = 0; h < 2; h++)
        #pragma unroll
        for (int i = 0; i < 4; i++) {
            u64* a = acc[h * 4 + i];
            float2 r0 = unpk(a[0]), r1 = unpk(a[1]), r2 = unpk(a[2]), r3 = unpk(a[3]);
            float v[8] = {r0.x, r0.y, r1.x, r1.y, r2.x, r2.y, r3.x, r3.y};
            float m = v[0];
            #pragma unroll
            for (int j = 1; j < 8; j++) m = fmaxf(m, v[j]);
            m = warpMax16(m);
            float e[8], s = 0.f;
            #pragma unroll
            for (int j = 0; j < 8; j++) { e[j] = __expf(v[j] - m); s += e[j]; }
            s = warpSum16(s);
            float inv = 1.0f / s;
            int q = q0 + h * 64 + ty * 4 + i;
            float* wrow = g_w + (((size_t)b * Q_ + q) * N_ + n) * L_;
            *(float4*)&wrow[tx * 4] =
                make_float4(e[0] * inv, e[1] * inv, e[2] * inv, e[3] * inv);
            *(float4*)&wrow[64 + tx * 4] =
                make_float4(e[4] * inv, e[5] * inv, e[6] * inv, e[7] * inv);
        }
}

// ---------------------------------------------------------------------------
// K4: per (n,b): S2[e,l] = sum_d Wcat[e, n*D+d] * src[l,d] -> g_s2[b][e][n][l]
// CTA tile 128 e x 128 l, kc = 32.  grid (2, N*B)
// ---------------------------------------------------------------------------
__global__ void __launch_bounds__(256, 2) k_s2(const float* __restrict__ Wcat) {
    const int nb = blockIdx.y;
    const int n = nb >> 5, b = nb & 31;
    const int e0 = blockIdx.x * 128;
    const float* src = g_src + (size_t)nb * L_ * D_;
    __shared__ __align__(16) float a_s[32][132];   // [d][e]
    __shared__ __align__(16) float b_s[32][132];   // [d][l]
    const int t  = threadIdx.x;
    const int ty = t >> 4, tx = t & 15;
    u64 acc[8][4] = {};
    for (int kd = 0; kd < D_; kd += 32) {
        __syncthreads();
        #pragma unroll
        for (int i = 0; i < 4; i++) {
            int idx = t + i * 256;               // 128e x 8(d4)
            int e = idx >> 3, d4 = (idx & 7) * 4;
            float4 v = *(const float4*)&Wcat[(size_t)(e0 + e) * (N_ * D_) + n * D_ + kd + d4];
            a_s[d4 + 0][e] = v.x; a_s[d4 + 1][e] = v.y;
            a_s[d4 + 2][e] = v.z; a_s[d4 + 3][e] = v.w;
        }
        #pragma unroll
        for (int i = 0; i < 4; i++) {
            int idx = t + i * 256;               // 128l x 8(d4)
            int l = idx >> 3, d4 = (idx & 7) * 4;
            float4 v = *(const float4*)&src[(size_t)l * D_ + kd + d4];
            b_s[d4 + 0][l] = v.x; b_s[d4 + 1][l] = v.y;
            b_s[d4 + 2][l] = v.z; b_s[d4 + 3][l] = v.w;
        }
        __syncthreads();
        #pragma unroll
        for (int d = 0; d < 32; d++) {
            float4 a0 = *(const float4*)&a_s[d][ty * 4];
            float4 a1 = *(const float4*)&a_s[d][ty * 4 + 64];
            const u64* p0 = (const u64*)&b_s[d][tx * 4];
            const u64* p1 = (const u64*)&b_s[d][tx * 4 + 64];
            u64 bv[4] = {p0[0], p0[1], p1[0], p1[1]};
            fma8x8p(acc, a0, a1, bv);
        }
    }
    #pragma unroll
    for (int h = 0; h < 2; h++)
        #pragma unroll
        for (int i = 0; i < 4; i++) {
            int e = e0 + h * 64 + ty * 4 + i;
            float* srow = g_s2 + (((size_t)b * D_ + e) * N_ + n) * L_;
            u64* a = acc[h * 4 + i];
            float2 r0 = unpk(a[0]), r1 = unpk(a[1]), r2 = unpk(a[2]), r3 = unpk(a[3]);
            *(float4*)&srow[tx * 4]      = make_float4(r0.x, r0.y, r1.x, r1.y);
            *(float4*)&srow[64 + tx * 4] = make_float4(r2.x, r2.y, r3.x, r3.y);
        }
}

// ---------------------------------------------------------------------------
// K5: per b: x[q,e] = sum_k w[b,q,k] * s2[b,e,k]  (K = 1280)
//     epilogue: + Wb, relu, + tgt, LayerNorm(eps=0) * gamma + beta -> out
// CTA tile 64 q x 256 e, kc = 16.  Each warp: 8 q rows, full 256-e row.
// ---------------------------------------------------------------------------
__global__ void __launch_bounds__(256, 2) k_out(const float* __restrict__ Wb,
                                                const float* __restrict__ gamma,
                                                const float* __restrict__ beta,
                                                float* __restrict__ out) {
    const int b  = blockIdx.y;
    const int q0 = blockIdx.x * 64;
    const float* wp = g_w  + (size_t)b * Q_ * K2_;
    const float* sp = g_s2 + (size_t)b * D_ * K2_;
    __shared__ __align__(16) float a_s[16][68];    // [k][q]  (64 q)
    __shared__ __align__(16) float b_s[16][260];   // [k][e]  (256 e)
    const int t  = threadIdx.x;
    const int ty = t >> 5, tx = t & 31;  // warp ty -> q rows q0+ty*8..+7; lane -> e {tx*4, 128+tx*4}
    u64 acc[8][4] = {};
    for (int k0 = 0; k0 < K2_; k0 += 16) {
        __syncthreads();
        // A: w[q][k] transposed: 64q x 16k = 256 float4, 1 per thread
        {
            int q = t >> 2, k4 = (t & 3) * 4;
            float4 v = *(const float4*)&wp[(size_t)(q0 + q) * K2_ + k0 + k4];
            a_s[k4 + 0][q] = v.x; a_s[k4 + 1][q] = v.y;
            a_s[k4 + 2][q] = v.z; a_s[k4 + 3][q] = v.w;
        }
        // B: s2[e][k] transposed: 256e x 16k = 1024 float4, 4 per thread
        #pragma unroll
        for (int i = 0; i < 4; i++) {
            int idx = t + i * 256;
            int e = idx >> 2, k4 = (idx & 3) * 4;
            float4 v = *(const float4*)&sp[(size_t)e * K2_ + k0 + k4];
            b_s[k4 + 0][e] = v.x; b_s[k4 + 1][e] = v.y;
            b_s[k4 + 2][e] = v.z; b_s[k4 + 3][e] = v.w;
        }
        __syncthreads();
        #pragma unroll
        for (int k = 0; k < 16; k++) {
            float4 a0 = *(const float4*)&a_s[k][ty * 8];
            float4 a1 = *(const float4*)&a_s[k][ty * 8 + 4];
            const u64* p0 = (const u64*)&b_s[k][tx * 4];
            const u64* p1 = (const u64*)&b_s[k][tx * 4 + 128];
            u64 bv[4] = {p0[0], p0[1], p1[0], p1[1]};
            fma8x8p(acc, a0, a1, bv);
        }
    }
    // epilogue
    float wb[8], gm[8], be[8];
    {
        float4 w0 = *(const float4*)&Wb[tx * 4];
        float4 w1 = *(const float4*)&Wb[tx * 4 + 128];
        float4 g0 = *(const float4*)&gamma[tx * 4];
        float4 g1 = *(const float4*)&gamma[tx * 4 + 128];
        float4 e0 = *(const float4*)&beta[tx * 4];
        float4 e1 = *(const float4*)&beta[tx * 4 + 128];
        wb[0]=w0.x; wb[1]=w0.y; wb[2]=w0.z; wb[3]=w0.w; wb[4]=w1.x; wb[5]=w1.y; wb[6]=w1.z; wb[7]=w1.w;
        gm[0]=g0.x; gm[1]=g0.y; gm[2]=g0.z; gm[3]=g0.w; gm[4]=g1.x; gm[5]=g1.y; gm[6]=g1.z; gm[7]=g1.w;
        be[0]=e0.x; be[1]=e0.y; be[2]=e0.z; be[3]=e0.w; be[4]=e1.x; be[5]=e1.y; be[6]=e1.z; be[7]=e1.w;
    }
    const float* tgt = g_tgt + (size_t)b * Q_ * D_;
    #pragma unroll
    for (int i = 0; i < 8; i++) {
        const int q = q0 + ty * 8 + i;
        u64* a = acc[i];
        float2 r0 = unpk(a[0]), r1 = unpk(a[1]), r2 = unpk(a[2]), r3 = unpk(a[3]);
        float av[8] = {r0.x, r0.y, r1.x, r1.y, r2.x, r2.y, r3.x, r3.y};
        float4 t0 = *(const float4*)&tgt[(size_t)q * D_ + tx * 4];
        float4 t1 = *(const float4*)&tgt[(size_t)q * D_ + tx * 4 + 128];
        float tv[8] = {t0.x, t0.y, t0.z, t0.w, t1.x, t1.y, t1.z, t1.w};
        float v[8], s = 0.f;
        #pragma unroll
        for (int j = 0; j < 8; j++) {
            v[j] = fmaxf(av[j] + wb[j], 0.f) + tv[j];
            s += v[j];
        }
        s = warpSum32(s);
        const float mu = s * (1.0f / 256.0f);
        float d2 = 0.f;
        #pragma unroll
        for (int j = 0; j < 8; j++) { float dd = v[j] - mu; d2 += dd * dd; }
        d2 = warpSum32(d2);
        const float rs = rsqrtf(d2 * (1.0f / 256.0f));
        float o[8];
        #pragma unroll
        for (int j = 0; j < 8; j++) o[j] = (v[j] - mu) * rs * gm[j] + be[j];
        float* orow = out + (size_t)(b * Q_ + q) * D_;
        *(float4*)&orow[tx * 4]       = make_float4(o[0], o[1], o[2], o[3]);
        *(float4*)&orow[tx * 4 + 128] = make_float4(o[4], o[5], o[6], o[7]);
    }
}

// ---------------------------------------------------------------------------
extern "C" void kernel_launch(void* const* d_in, const int* in_sizes, int n_in,
                              void* d_out, int out_size) {
    const float* input    = (const float*)d_in[0];  // [B, D, 32, 32]
    const float* contexts = (const float*)d_in[1];  // [N, B, C, L]
    const float* Wc       = (const float*)d_in[2];  // [D, C]
    const float* Wcat     = (const float*)d_in[3];  // [D, N*D]
    const float* Wb       = (const float*)d_in[4];  // [D]
    const float* gamma    = (const float*)d_in[5];  // [D]
    const float* beta     = (const float*)d_in[6];  // [D]
    float* out = (float*)d_out;                     // [B, Q, D]

    k_transpose<<<dim3(Q_ / 32, D_ / 32, B_), dim3(32, 8)>>>(input);
    k_source   <<<dim3(2,        N_ * B_),    256>>>(contexts, Wc);
    k_attn     <<<dim3(Q_ / 128, N_ * B_),    256>>>();
    k_s2       <<<dim3(2,        N_ * B_),    256>>>(Wcat);
    k_out      <<<dim3(Q_ / 64,  B_),         256>>>(Wb, gamma, beta, out);
}